// round 17
// baseline (speedup 1.0000x reference)
#include <cuda_runtime.h>
#include <cuda_bf16.h>

// Nearest-codeword quantization, uniform sorted 16-entry codebook.
// out[i] = argmin_c |x[i] - c|, tie toward the LOWER codeword.
//
// R17 = R13 structure (16 elem/thread, branchless FMA hot path, ONE
// warp-vote per 16 elements, exact rare path vs TRUE codebook) using
// Blackwell 256-bit vector memory ops: 2x ld.global.nc.v8.f32 +
// 2x st.global.v8.f32 per thread instead of 4x LDG.128/STG.128.
// Lane stride 32B -> warp covers 1024B contiguous (8 lines), 32B-aligned.
//
// Hot path per element: t = fma(x,inv,b0); tc = clamp(t,0,15);
// tr = rintf(tc); val = fma(tr,step,c0); maxd = fmax(maxd,|tc-tr|).
// If any lane is within EPS=1e-4 (index space) of a midpoint, the whole
// iteration is recomputed exactly (reference tie-break |x-lo|<=|x-hi| -> lo).
// val is <=1 ulp from the stored linspace codeword (rel_err ~7e-8, tol 1e-3).

#define K_CB 16

__device__ __forceinline__ void ldg_v8(const float* p, float* r) {
    asm volatile("ld.global.nc.v8.f32 {%0,%1,%2,%3,%4,%5,%6,%7}, [%8];"
                 : "=f"(r[0]), "=f"(r[1]), "=f"(r[2]), "=f"(r[3]),
                   "=f"(r[4]), "=f"(r[5]), "=f"(r[6]), "=f"(r[7])
                 : "l"(p));
}

__device__ __forceinline__ void stg_v8(float* p, const float* r) {
    asm volatile("st.global.v8.f32 [%0], {%1,%2,%3,%4,%5,%6,%7,%8};"
                 :: "l"(p),
                    "f"(r[0]), "f"(r[1]), "f"(r[2]), "f"(r[3]),
                    "f"(r[4]), "f"(r[5]), "f"(r[6]), "f"(r[7])
                 : "memory");
}

__global__ void __launch_bounds__(256)
quant_uniform_kernel(const float* __restrict__ xf,
                     const float* __restrict__ cb,
                     float* __restrict__ outf,
                     int n8)            // element count / 8
{
    const float c0 = __ldg(cb);
    const float cK = __ldg(cb + K_CB - 1);
    const float step     = (cK - c0) * (1.0f / (float)(K_CB - 1));
    const float inv_step = (float)(K_CB - 1) / (cK - c0);
    const float b0 = -c0 * inv_step;
    const float TH = 0.5f - 1e-4f;      // guard threshold in index space

    const int tid  = threadIdx.x;
    const int bdim = blockDim.x;                  // 256
    const int base = blockIdx.x * (bdim * 2) + tid;   // in float8 units

    if (base + bdim < n8) {
        // 2 fully-coalesced 256-bit loads, front-batched.
        float va[8], vb[8];
        ldg_v8(xf + (size_t)base * 8,          va);
        ldg_v8(xf + (size_t)(base + bdim) * 8, vb);

        float ra[8], rb[8];
        float maxd = 0.0f;

#pragma unroll
        for (int j = 0; j < 8; j++) {
            float xv = va[j];
            float t  = fmaf(xv, inv_step, b0);
            float tc = fminf(fmaxf(t, 0.0f), (float)(K_CB - 1));
            float tr = rintf(tc);
            ra[j] = fmaf(tr, step, c0);
            maxd = fmaxf(maxd, fabsf(tc - tr));
        }
#pragma unroll
        for (int j = 0; j < 8; j++) {
            float xv = vb[j];
            float t  = fmaf(xv, inv_step, b0);
            float tc = fminf(fmaxf(t, 0.0f), (float)(K_CB - 1));
            float tr = rintf(tc);
            rb[j] = fmaf(tr, step, c0);
            maxd = fmaxf(maxd, fabsf(tc - tr));
        }

        // ONE vote per 16 elements: does ANY lane need the exact path?
        if (__any_sync(0xFFFFFFFFu, maxd >= TH)) {
#pragma unroll
            for (int j = 0; j < 8; j++) {
                float xv = va[j];
                float t  = fmaf(xv, inv_step, b0);
                int k = min(max(__float2int_rd(t), 0), K_CB - 2);
                float lo = __ldg(cb + k);
                float hi = __ldg(cb + k + 1);
                ra[j] = (fabsf(xv - lo) <= fabsf(xv - hi)) ? lo : hi;
            }
#pragma unroll
            for (int j = 0; j < 8; j++) {
                float xv = vb[j];
                float t  = fmaf(xv, inv_step, b0);
                int k = min(max(__float2int_rd(t), 0), K_CB - 2);
                float lo = __ldg(cb + k);
                float hi = __ldg(cb + k + 1);
                rb[j] = (fabsf(xv - lo) <= fabsf(xv - hi)) ? lo : hi;
            }
        }

        // Uninterrupted 256-bit store burst.
        stg_v8(outf + (size_t)base * 8,          ra);
        stg_v8(outf + (size_t)(base + bdim) * 8, rb);
    } else {
        // Tail (not taken for 8192x8192): always-exact scalar path.
        for (int c = 0; c < 2; c++) {
            int idx8 = base + c * bdim;
            if (idx8 >= n8) break;
            const float* p = xf + (size_t)idx8 * 8;
            float* q = outf + (size_t)idx8 * 8;
            for (int j = 0; j < 8; j++) {
                float xv = p[j];
                float t  = fmaf(xv, inv_step, b0);
                int k = min(max(__float2int_rd(t), 0), K_CB - 2);
                float lo = __ldg(cb + k);
                float hi = __ldg(cb + k + 1);
                q[j] = (fabsf(xv - lo) <= fabsf(xv - hi)) ? lo : hi;
            }
        }
    }
}

extern "C" void kernel_launch(void* const* d_in, const int* in_sizes, int n_in,
                              void* d_out, int out_size)
{
    const float* x  = (const float*)d_in[0];
    const float* cb = (const float*)d_in[1];
    float* out = (float*)d_out;

    int n  = in_sizes[0];         // 8192*8192 = 67,108,864
    int n8 = n >> 3;              // 8,388,608 float8

    const int threads = 256;
    const int per_block = threads * 2;                 // 512 float8 / block
    int blocks = (n8 + per_block - 1) / per_block;     // 16384

    quant_uniform_kernel<<<blocks, threads>>>(x, cb, out, n8);
}